// round 1
// baseline (speedup 1.0000x reference)
#include <cuda_runtime.h>
#include <math.h>

#define Ln 6
#define Bt 2
#define Qn 300
#define Dn 256
#define LP1 7

// Device-global scratch (no allocations allowed in kernel_launch)
__device__ float g_Qall[LP1*Bt*Qn*Dn];   // 4.3 MB
__device__ float g_Kall[LP1*Bt*Qn*Dn];
__device__ float g_Aproj[LP1*Bt*Qn*Dn];  // Q_all @ W1[:256]
__device__ float g_Bproj[LP1*Bt*Qn*Dn];  // K_all @ W1[256:]
__device__ float g_gq[LP1*Bt*Qn];        // Q_all . wa + bg
__device__ float g_gk[LP1*Bt*Qn];        // K_all . wb

// Generic row-tile GEMM: out[r,e] = sum_d src[r,d]*W[d,e] (+bias[e])
// ROWS rows per block, 256 threads (thread = output column e).
template<int ROWS>
__device__ __forceinline__ void gemm_tile(const float* __restrict__ src,
                                          const float* __restrict__ W,
                                          const float* __restrict__ bias,
                                          float* __restrict__ out)
{
    __shared__ float ssrc[ROWS*Dn];
    int tid = threadIdx.x;
    // flat copy of ROWS x 256 (rows contiguous)
    for (int idx = tid; idx < ROWS*Dn/4; idx += 256)
        ((float4*)ssrc)[idx] = ((const float4*)src)[idx];
    __syncthreads();

    int e = tid;
    float acc[ROWS];
    #pragma unroll
    for (int r = 0; r < ROWS; r++) acc[r] = 0.f;

    for (int d = 0; d < Dn; d += 4) {
        float w0 = W[(d+0)*Dn + e];
        float w1 = W[(d+1)*Dn + e];
        float w2 = W[(d+2)*Dn + e];
        float w3 = W[(d+3)*Dn + e];
        #pragma unroll
        for (int r = 0; r < ROWS; r++) {
            float4 s4 = *(const float4*)&ssrc[r*Dn + d];   // broadcast LDS.128
            acc[r] = fmaf(s4.x, w0, acc[r]);
            acc[r] = fmaf(s4.y, w1, acc[r]);
            acc[r] = fmaf(s4.z, w2, acc[r]);
            acc[r] = fmaf(s4.w, w3, acc[r]);
        }
    }
    float bv = bias ? bias[e] : 0.f;
    #pragma unroll
    for (int r = 0; r < ROWS; r++) out[r*Dn + e] = acc[r] + bv;
}

// grid (10 row-tiles of 30, 14 = l*2+b, 2 = Q/K)
__global__ void __launch_bounds__(256)
kernel_qk(const float* __restrict__ hs,
          const float* __restrict__ Wq,  const float* __restrict__ bq,
          const float* __restrict__ Wk,  const float* __restrict__ bk,
          const float* __restrict__ Wsub,const float* __restrict__ bsub,
          const float* __restrict__ Wobj,const float* __restrict__ bobj)
{
    int tile = blockIdx.x;        // 0..9
    int lb   = blockIdx.y;        // 0..13
    int isK  = blockIdx.z;
    int l = lb >> 1, b = lb & 1;
    int srcl = (l < Ln) ? l : (Ln - 1);
    const float* src = hs + ((size_t)(srcl*Bt + b)*Qn + tile*30)*Dn;
    const float* W; const float* bias; float* out;
    if (!isK) {
        if (l < Ln) { W = Wq + (size_t)l*Dn*Dn; bias = bq + l*Dn; }
        else        { W = Wsub;                 bias = bsub; }
        out = g_Qall;
    } else {
        if (l < Ln) { W = Wk + (size_t)l*Dn*Dn; bias = bk + l*Dn; }
        else        { W = Wobj;                 bias = bobj; }
        out = g_Kall;
    }
    out += ((size_t)(l*Bt + b)*Qn + tile*30)*Dn;
    gemm_tile<30>(src, W, bias, out);
}

// grid (140 row-tiles of 30 over 4200 rows, 2 = A/B)
__global__ void __launch_bounds__(256)
kernel_ab(const float* __restrict__ W1)
{
    int tile = blockIdx.x;
    int isB  = blockIdx.y;
    const float* src = (isB ? g_Kall : g_Qall) + (size_t)tile*30*Dn;
    const float* W   = W1 + (isB ? Dn*Dn : 0);   // W1 is (512,256): rows 0..255 / 256..511
    float* out = (isB ? g_Bproj : g_Aproj) + (size_t)tile*30*Dn;
    gemm_tile<30>(src, W, nullptr, out);
}

// warp-per-row dot products: gq = Qall.wa + bg ; gk = Kall.wb
__global__ void kernel_g(const float* __restrict__ Wg, const float* __restrict__ bg)
{
    int warp = threadIdx.x >> 5, lane = threadIdx.x & 31;
    int row = blockIdx.x*8 + warp;
    if (row >= LP1*Bt*Qn) return;
    int isK = blockIdx.y;
    const float* src = (isK ? g_Kall : g_Qall) + (size_t)row*Dn;
    const float* w   = Wg + (isK ? Dn : 0);
    float s = 0.f;
    #pragma unroll
    for (int u = 0; u < 8; u++) s = fmaf(src[lane + 32*u], w[lane + 32*u], s);
    #pragma unroll
    for (int off = 16; off > 0; off >>= 1) s += __shfl_xor_sync(0xffffffffu, s, off);
    if (lane == 0) {
        if (isK) g_gk[row] = s;
        else     g_gq[row] = s + bg[0];
    }
}

// Main fused kernel: 8i x 4j = 32 pairs per block.
// Phase 1: h1[p,e] = relu( sum_l gate[l,p]*(A[l,i,e]+B[l,j,e]) + b1[e] ) -> smem
// Phase 2: pred[p] = relu(h1[p,:] @ W2 + b2) . w3 + b3 -> out (6 layer copies)
__global__ void __launch_bounds__(256)
kernel_main(const float* __restrict__ b1, const float* __restrict__ W2,
            const float* __restrict__ b2, const float* __restrict__ W3,
            const float* __restrict__ b3, float* __restrict__ out)
{
    const int TI = 8, TJ = 4, NP = 32;
    __shared__ float h1s[NP*Dn];     // 32 KB
    __shared__ float gsh[LP1*NP];    // gates

    int j0 = blockIdx.x*TJ;
    int i0 = blockIdx.y*TI;
    int b  = blockIdx.z;
    int tid = threadIdx.x;

    // gates (bg already folded into gq)
    if (tid < LP1*NP) {
        int l = tid / NP, p = tid % NP;
        int ii = p >> 2, jj = p & 3;
        int i = i0 + ii, j = j0 + jj;
        float g = 0.f;
        if (i < Qn && j < Qn) {
            float z = g_gq[(l*Bt + b)*Qn + i] + g_gk[(l*Bt + b)*Qn + j];
            g = 1.f / (1.f + expf(-z));
        }
        gsh[tid] = g;
    }
    __syncthreads();

    // ---- phase 1: gated combine (thread = column e) ----
    int e = tid;
    float acc[NP];
    #pragma unroll
    for (int p = 0; p < NP; p++) acc[p] = 0.f;

    #pragma unroll
    for (int l = 0; l < LP1; l++) {
        const float* Ab = g_Aproj + (size_t)(l*Bt + b)*Qn*Dn;
        const float* Bb = g_Bproj + (size_t)(l*Bt + b)*Qn*Dn;
        float av[TI], bv[TJ];
        #pragma unroll
        for (int ii = 0; ii < TI; ii++) {
            int i = min(i0 + ii, Qn - 1);
            av[ii] = Ab[(size_t)i*Dn + e];
        }
        #pragma unroll
        for (int jj = 0; jj < TJ; jj++) {
            int j = min(j0 + jj, Qn - 1);
            bv[jj] = Bb[(size_t)j*Dn + e];
        }
        #pragma unroll
        for (int ii = 0; ii < TI; ii++)
            #pragma unroll
            for (int jj = 0; jj < TJ; jj++)
                acc[ii*TJ + jj] = fmaf(gsh[l*NP + ii*TJ + jj], av[ii] + bv[jj], acc[ii*TJ + jj]);
    }
    float b1e = b1[e];
    #pragma unroll
    for (int p = 0; p < NP; p++) h1s[p*Dn + e] = fmaxf(acc[p] + b1e, 0.f);
    __syncthreads();

    // ---- phase 2: 32x256x256 GEMM + relu + dot(w3) ----
    int lanex = tid & 31;
    int wid   = tid >> 5;             // warp handles pairs wid*4 .. wid*4+3
    int ncol0 = lanex * 8;            // 8 contiguous output columns per thread

    float acc2[4][8];
    #pragma unroll
    for (int pp = 0; pp < 4; pp++)
        #pragma unroll
        for (int cc = 0; cc < 8; cc++) acc2[pp][cc] = 0.f;

    const float4* W2v = (const float4*)W2;

    for (int k0 = 0; k0 < Dn; k0 += 4) {
        float4 hv[4];
        #pragma unroll
        for (int pp = 0; pp < 4; pp++)
            hv[pp] = *(const float4*)&h1s[(wid*4 + pp)*Dn + k0];   // broadcast LDS.128
        #pragma unroll
        for (int u = 0; u < 4; u++) {
            int base = ((k0 + u)*Dn + ncol0) >> 2;
            float4 w0 = W2v[base];
            float4 w1 = W2v[base + 1];
            #pragma unroll
            for (int pp = 0; pp < 4; pp++) {
                float h = (u == 0) ? hv[pp].x : (u == 1) ? hv[pp].y
                        : (u == 2) ? hv[pp].z : hv[pp].w;
                acc2[pp][0] = fmaf(h, w0.x, acc2[pp][0]);
                acc2[pp][1] = fmaf(h, w0.y, acc2[pp][1]);
                acc2[pp][2] = fmaf(h, w0.z, acc2[pp][2]);
                acc2[pp][3] = fmaf(h, w0.w, acc2[pp][3]);
                acc2[pp][4] = fmaf(h, w1.x, acc2[pp][4]);
                acc2[pp][5] = fmaf(h, w1.y, acc2[pp][5]);
                acc2[pp][6] = fmaf(h, w1.z, acc2[pp][6]);
                acc2[pp][7] = fmaf(h, w1.w, acc2[pp][7]);
            }
        }
    }

    float b2v[8], w3v[8];
    #pragma unroll
    for (int cc = 0; cc < 8; cc++) {
        b2v[cc] = b2[ncol0 + cc];
        w3v[cc] = W3[ncol0 + cc];
    }
    float b3v = b3[0];

    #pragma unroll
    for (int pp = 0; pp < 4; pp++) {
        float s = 0.f;
        #pragma unroll
        for (int cc = 0; cc < 8; cc++) {
            float h2 = fmaxf(acc2[pp][cc] + b2v[cc], 0.f);
            s = fmaf(h2, w3v[cc], s);
        }
        #pragma unroll
        for (int off = 16; off > 0; off >>= 1) s += __shfl_xor_sync(0xffffffffu, s, off);
        if (lanex == 0) {
            int p = wid*4 + pp;
            int i = i0 + (p >> 2), j = j0 + (p & 3);
            if (i < Qn && j < Qn) {
                float pred = s + b3v;
                #pragma unroll
                for (int lay = 0; lay < Ln; lay++)
                    out[((size_t)(lay*Bt + b)*Qn + i)*Qn + j] = pred;
            }
        }
    }
}

extern "C" void kernel_launch(void* const* d_in, const int* in_sizes, int n_in,
                              void* d_out, int out_size)
{
    const float* hs   = (const float*)d_in[0];
    const float* Wq   = (const float*)d_in[1];
    const float* bq   = (const float*)d_in[2];
    const float* Wk   = (const float*)d_in[3];
    const float* bk   = (const float*)d_in[4];
    const float* Wsub = (const float*)d_in[5];
    const float* bsub = (const float*)d_in[6];
    const float* Wobj = (const float*)d_in[7];
    const float* bobj = (const float*)d_in[8];
    const float* Wg   = (const float*)d_in[9];
    const float* bg   = (const float*)d_in[10];
    const float* W1   = (const float*)d_in[11];
    const float* b1   = (const float*)d_in[12];
    const float* W2   = (const float*)d_in[13];
    const float* b2   = (const float*)d_in[14];
    const float* W3   = (const float*)d_in[15];
    const float* b3   = (const float*)d_in[16];
    float* out = (float*)d_out;

    kernel_qk  <<<dim3(10, 14, 2), 256>>>(hs, Wq, bq, Wk, bk, Wsub, bsub, Wobj, bobj);
    kernel_ab  <<<dim3(140, 2),    256>>>(W1);
    kernel_g   <<<dim3(525, 2),    256>>>(Wg, bg);
    kernel_main<<<dim3(75, 38, 2), 256>>>(b1, W2, b2, W3, b3, out);
}

// round 2
// speedup vs baseline: 1.3767x; 1.3767x over previous
#include <cuda_runtime.h>
#include <math.h>

#define Ln 6
#define Bt 2
#define Qn 300
#define Dn 256
#define LP1 7

// Device-global scratch (no allocations allowed in kernel_launch)
__device__ float g_Qall[LP1*Bt*Qn*Dn];   // 4.3 MB
__device__ float g_Kall[LP1*Bt*Qn*Dn];
__device__ float g_Aproj[LP1*Bt*Qn*Dn];  // Q_all @ W1[:256]
__device__ float g_Bproj[LP1*Bt*Qn*Dn];  // K_all @ W1[256:]
__device__ float g_gq[LP1*Bt*Qn];        // Q_all . wa + bg
__device__ float g_gk[LP1*Bt*Qn];        // K_all . wb

typedef unsigned long long u64;

__device__ __forceinline__ u64 pack2(float x) {
    u64 r;
    unsigned xi = __float_as_uint(x);
    asm("mov.b64 %0, {%1, %1};" : "=l"(r) : "r"(xi));
    return r;
}
__device__ __forceinline__ u64 fma2(u64 a, u64 b, u64 c) {
    u64 d;
    asm("fma.rn.f32x2 %0, %1, %2, %3;" : "=l"(d) : "l"(a), "l"(b), "l"(c));
    return d;
}
__device__ __forceinline__ u64 add2(u64 a, u64 b) {
    u64 d;
    asm("add.rn.f32x2 %0, %1, %2;" : "=l"(d) : "l"(a), "l"(b));
    return d;
}
__device__ __forceinline__ float lo32(u64 v) { return __uint_as_float((unsigned)(v & 0xffffffffull)); }
__device__ __forceinline__ float hi32(u64 v) { return __uint_as_float((unsigned)(v >> 32)); }

// Generic row-tile GEMM: out[r,e] = sum_d src[r,d]*W[d,e] (+bias[e])
// ROWS rows per block, 256 threads (thread = output column e).
template<int ROWS>
__device__ __forceinline__ void gemm_tile(const float* __restrict__ src,
                                          const float* __restrict__ W,
                                          const float* __restrict__ bias,
                                          float* __restrict__ out)
{
    __shared__ float ssrc[ROWS*Dn];
    int tid = threadIdx.x;
    for (int idx = tid; idx < ROWS*Dn/4; idx += 256)
        ((float4*)ssrc)[idx] = ((const float4*)src)[idx];
    __syncthreads();

    int e = tid;
    float acc[ROWS];
    #pragma unroll
    for (int r = 0; r < ROWS; r++) acc[r] = 0.f;

    for (int d = 0; d < Dn; d += 4) {
        float w0 = W[(d+0)*Dn + e];
        float w1 = W[(d+1)*Dn + e];
        float w2 = W[(d+2)*Dn + e];
        float w3 = W[(d+3)*Dn + e];
        #pragma unroll
        for (int r = 0; r < ROWS; r++) {
            float4 s4 = *(const float4*)&ssrc[r*Dn + d];
            acc[r] = fmaf(s4.x, w0, acc[r]);
            acc[r] = fmaf(s4.y, w1, acc[r]);
            acc[r] = fmaf(s4.z, w2, acc[r]);
            acc[r] = fmaf(s4.w, w3, acc[r]);
        }
    }
    float bv = bias ? bias[e] : 0.f;
    #pragma unroll
    for (int r = 0; r < ROWS; r++) out[r*Dn + e] = acc[r] + bv;
}

__global__ void __launch_bounds__(256)
kernel_qk(const float* __restrict__ hs,
          const float* __restrict__ Wq,  const float* __restrict__ bq,
          const float* __restrict__ Wk,  const float* __restrict__ bk,
          const float* __restrict__ Wsub,const float* __restrict__ bsub,
          const float* __restrict__ Wobj,const float* __restrict__ bobj)
{
    int tile = blockIdx.x;        // 0..9
    int lb   = blockIdx.y;        // 0..13
    int isK  = blockIdx.z;
    int l = lb >> 1, b = lb & 1;
    int srcl = (l < Ln) ? l : (Ln - 1);
    const float* src = hs + ((size_t)(srcl*Bt + b)*Qn + tile*30)*Dn;
    const float* W; const float* bias; float* out;
    if (!isK) {
        if (l < Ln) { W = Wq + (size_t)l*Dn*Dn; bias = bq + l*Dn; }
        else        { W = Wsub;                 bias = bsub; }
        out = g_Qall;
    } else {
        if (l < Ln) { W = Wk + (size_t)l*Dn*Dn; bias = bk + l*Dn; }
        else        { W = Wobj;                 bias = bobj; }
        out = g_Kall;
    }
    out += ((size_t)(l*Bt + b)*Qn + tile*30)*Dn;
    gemm_tile<30>(src, W, bias, out);
}

__global__ void __launch_bounds__(256)
kernel_ab(const float* __restrict__ W1)
{
    int tile = blockIdx.x;
    int isB  = blockIdx.y;
    const float* src = (isB ? g_Kall : g_Qall) + (size_t)tile*30*Dn;
    const float* W   = W1 + (isB ? Dn*Dn : 0);
    float* out = (isB ? g_Bproj : g_Aproj) + (size_t)tile*30*Dn;
    gemm_tile<30>(src, W, nullptr, out);
}

__global__ void kernel_g(const float* __restrict__ Wg, const float* __restrict__ bg)
{
    int warp = threadIdx.x >> 5, lane = threadIdx.x & 31;
    int row = blockIdx.x*8 + warp;
    if (row >= LP1*Bt*Qn) return;
    int isK = blockIdx.y;
    const float* src = (isK ? g_Kall : g_Qall) + (size_t)row*Dn;
    const float* w   = Wg + (isK ? Dn : 0);
    float s = 0.f;
    #pragma unroll
    for (int u = 0; u < 8; u++) s = fmaf(src[lane + 32*u], w[lane + 32*u], s);
    #pragma unroll
    for (int off = 16; off > 0; off >>= 1) s += __shfl_xor_sync(0xffffffffu, s, off);
    if (lane == 0) {
        if (isK) g_gk[row] = s;
        else     g_gq[row] = s + bg[0];
    }
}

// Main fused kernel: 8i x 4j = 32 pairs per block, 128 threads.
// Phase 1: h1[p,e] = relu( sum_l gate[l,p]*(A[l,i,e]+B[l,j,e]) + b1[e] ) -> smem
//          (f32x2 packed over adjacent column pairs)
// Phase 2: pred[p] = relu(h1[p,:] @ W2 + b2) . w3 + b3
//          warp handles 8 pairs, lane handles 8 cols, fma.rn.f32x2.
__global__ void __launch_bounds__(128)
kernel_main(const float* __restrict__ b1, const float* __restrict__ W2,
            const float* __restrict__ b2, const float* __restrict__ W3,
            const float* __restrict__ b3, float* __restrict__ out)
{
    const int TI = 8, TJ = 4, NP = 32;
    __shared__ float h1s[NP*Dn];     // 32 KB
    __shared__ u64   gsh2[LP1*NP];   // gates packed {g,g}

    int j0 = blockIdx.x*TJ;
    int i0 = blockIdx.y*TI;
    int b  = blockIdx.z;
    int tid = threadIdx.x;

    // gates (bg already folded into gq), duplicated-packed
    for (int t = tid; t < LP1*NP; t += 128) {
        int l = t / NP, p = t % NP;
        int ii = p >> 2, jj = p & 3;
        int i = i0 + ii, j = j0 + jj;
        float g = 0.f;
        if (i < Qn && j < Qn) {
            float z = g_gq[(l*Bt + b)*Qn + i] + g_gk[(l*Bt + b)*Qn + j];
            g = 1.f / (1.f + expf(-z));
        }
        gsh2[t] = pack2(g);
    }
    __syncthreads();

    // ---- phase 1: gated combine, thread = adjacent col pair (2*tid, 2*tid+1) ----
    {
        int e2 = 2*tid;
        u64 acc[NP];
        #pragma unroll
        for (int p = 0; p < NP; p++) acc[p] = 0ull;

        #pragma unroll
        for (int l = 0; l < LP1; l++) {
            const float* Ab = g_Aproj + (size_t)(l*Bt + b)*Qn*Dn;
            const float* Bb = g_Bproj + (size_t)(l*Bt + b)*Qn*Dn;
            u64 avp[TI], bvp[TJ];
            #pragma unroll
            for (int ii = 0; ii < TI; ii++) {
                int i = min(i0 + ii, Qn - 1);
                avp[ii] = *(const u64*)&Ab[(size_t)i*Dn + e2];
            }
            #pragma unroll
            for (int jj = 0; jj < TJ; jj++) {
                int j = min(j0 + jj, Qn - 1);
                bvp[jj] = *(const u64*)&Bb[(size_t)j*Dn + e2];
            }
            #pragma unroll
            for (int ii = 0; ii < TI; ii++)
                #pragma unroll
                for (int jj = 0; jj < TJ; jj++) {
                    int p = ii*TJ + jj;
                    acc[p] = fma2(gsh2[l*NP + p], add2(avp[ii], bvp[jj]), acc[p]);
                }
        }
        u64 b1p = *(const u64*)&b1[e2];
        #pragma unroll
        for (int p = 0; p < NP; p++) {
            u64 v = add2(acc[p], b1p);
            float lo = fmaxf(lo32(v), 0.f);
            float hi = fmaxf(hi32(v), 0.f);
            *(float2*)&h1s[p*Dn + e2] = make_float2(lo, hi);
        }
    }
    __syncthreads();

    // ---- phase 2: 32x256x256 GEMM (f32x2) + relu + dot(w3) ----
    int lanex = tid & 31;
    int wid   = tid >> 5;             // warp handles pairs wid*8 .. wid*8+7
    int ncol0 = lanex * 8;            // 8 contiguous output columns per thread

    u64 acc2[8][4];
    #pragma unroll
    for (int pp = 0; pp < 8; pp++)
        #pragma unroll
        for (int c = 0; c < 4; c++) acc2[pp][c] = 0ull;

    for (int k0 = 0; k0 < Dn; k0 += 4) {
        float hv[8][4];
        #pragma unroll
        for (int pp = 0; pp < 8; pp++)
            *(float4*)hv[pp] = *(const float4*)&h1s[(wid*8 + pp)*Dn + k0];  // broadcast LDS.128
        #pragma unroll
        for (int u = 0; u < 4; u++) {
            const ulonglong2* Wp = (const ulonglong2*)(W2 + (size_t)(k0 + u)*Dn + ncol0);
            ulonglong2 wA = Wp[0];
            ulonglong2 wB = Wp[1];
            #pragma unroll
            for (int pp = 0; pp < 8; pp++) {
                u64 hp = pack2(hv[pp][u]);
                acc2[pp][0] = fma2(hp, wA.x, acc2[pp][0]);
                acc2[pp][1] = fma2(hp, wA.y, acc2[pp][1]);
                acc2[pp][2] = fma2(hp, wB.x, acc2[pp][2]);
                acc2[pp][3] = fma2(hp, wB.y, acc2[pp][3]);
            }
        }
    }

    float b2v[8], w3v[8];
    #pragma unroll
    for (int cc = 0; cc < 8; cc++) {
        b2v[cc] = b2[ncol0 + cc];
        w3v[cc] = W3[ncol0 + cc];
    }
    float b3v = b3[0];

    #pragma unroll
    for (int pp = 0; pp < 8; pp++) {
        float s = 0.f;
        #pragma unroll
        for (int c = 0; c < 4; c++) {
            float h2a = fmaxf(lo32(acc2[pp][c]) + b2v[2*c],   0.f);
            float h2b = fmaxf(hi32(acc2[pp][c]) + b2v[2*c+1], 0.f);
            s = fmaf(h2a, w3v[2*c],   s);
            s = fmaf(h2b, w3v[2*c+1], s);
        }
        #pragma unroll
        for (int off = 16; off > 0; off >>= 1) s += __shfl_xor_sync(0xffffffffu, s, off);
        if (lanex == 0) {
            int p = wid*8 + pp;
            int i = i0 + (p >> 2), j = j0 + (p & 3);
            if (i < Qn && j < Qn) {
                float pred = s + b3v;
                #pragma unroll
                for (int lay = 0; lay < Ln; lay++)
                    out[((size_t)(lay*Bt + b)*Qn + i)*Qn + j] = pred;
            }
        }
    }
}

extern "C" void kernel_launch(void* const* d_in, const int* in_sizes, int n_in,
                              void* d_out, int out_size)
{
    const float* hs   = (const float*)d_in[0];
    const float* Wq   = (const float*)d_in[1];
    const float* bq   = (const float*)d_in[2];
    const float* Wk   = (const float*)d_in[3];
    const float* bk   = (const float*)d_in[4];
    const float* Wsub = (const float*)d_in[5];
    const float* bsub = (const float*)d_in[6];
    const float* Wobj = (const float*)d_in[7];
    const float* bobj = (const float*)d_in[8];
    const float* Wg   = (const float*)d_in[9];
    const float* bg   = (const float*)d_in[10];
    const float* W1   = (const float*)d_in[11];
    const float* b1   = (const float*)d_in[12];
    const float* W2   = (const float*)d_in[13];
    const float* b2   = (const float*)d_in[14];
    const float* W3   = (const float*)d_in[15];
    const float* b3   = (const float*)d_in[16];
    float* out = (float*)d_out;

    kernel_qk  <<<dim3(10, 14, 2), 256>>>(hs, Wq, bq, Wk, bk, Wsub, bsub, Wobj, bobj);
    kernel_ab  <<<dim3(140, 2),    256>>>(W1);
    kernel_g   <<<dim3(525, 2),    256>>>(Wg, bg);
    kernel_main<<<dim3(75, 38, 2), 128>>>(b1, W2, b2, W3, b3, out);
}

// round 4
// speedup vs baseline: 2.4695x; 1.7938x over previous
#include <cuda_runtime.h>
#include <cuda_bf16.h>
#include <math.h>

#define Ln 6
#define Bt 2
#define Qn 300
#define Dn 256
#define LP1 7

// ---------------- device scratch (no allocs allowed) ----------------
__device__ float g_Qall[LP1*Bt*Qn*Dn];
__device__ float g_Kall[LP1*Bt*Qn*Dn];
__device__ float g_Aproj[LP1*Bt*Qn*Dn];
__device__ float g_Bproj[LP1*Bt*Qn*Dn];
__device__ float g_gq[LP1*Bt*Qn];
__device__ float g_gk[LP1*Bt*Qn];
// W2 (256x256) as bf16 hi/lo in mma.m16n8k16 B-fragment order:
// idx = ((kt*32 + gnt)*32 + lane), each entry = uint4 {bhi_r0, bhi_r1, blo_r0, blo_r1}
__device__ uint4 g_W2frag[16*32*32];   // 256 KB

// ---------------- small GEMM helper (unchanged from passing R2) ----------------
template<int ROWS>
__device__ __forceinline__ void gemm_tile(const float* __restrict__ src,
                                          const float* __restrict__ W,
                                          const float* __restrict__ bias,
                                          float* __restrict__ out)
{
    __shared__ float ssrc[ROWS*Dn];
    int tid = threadIdx.x;
    for (int idx = tid; idx < ROWS*Dn/4; idx += 256)
        ((float4*)ssrc)[idx] = ((const float4*)src)[idx];
    __syncthreads();

    int e = tid;
    float acc[ROWS];
    #pragma unroll
    for (int r = 0; r < ROWS; r++) acc[r] = 0.f;

    for (int d = 0; d < Dn; d += 4) {
        float w0 = W[(d+0)*Dn + e];
        float w1 = W[(d+1)*Dn + e];
        float w2 = W[(d+2)*Dn + e];
        float w3 = W[(d+3)*Dn + e];
        #pragma unroll
        for (int r = 0; r < ROWS; r++) {
            float4 s4 = *(const float4*)&ssrc[r*Dn + d];
            acc[r] = fmaf(s4.x, w0, acc[r]);
            acc[r] = fmaf(s4.y, w1, acc[r]);
            acc[r] = fmaf(s4.z, w2, acc[r]);
            acc[r] = fmaf(s4.w, w3, acc[r]);
        }
    }
    float bv = bias ? bias[e] : 0.f;
    #pragma unroll
    for (int r = 0; r < ROWS; r++) out[r*Dn + e] = acc[r] + bv;
}

__global__ void __launch_bounds__(256)
kernel_qk(const float* __restrict__ hs,
          const float* __restrict__ Wq,  const float* __restrict__ bq,
          const float* __restrict__ Wk,  const float* __restrict__ bk,
          const float* __restrict__ Wsub,const float* __restrict__ bsub,
          const float* __restrict__ Wobj,const float* __restrict__ bobj)
{
    int tile = blockIdx.x;
    int lb   = blockIdx.y;
    int isK  = blockIdx.z;
    int l = lb >> 1, b = lb & 1;
    int srcl = (l < Ln) ? l : (Ln - 1);
    const float* src = hs + ((size_t)(srcl*Bt + b)*Qn + tile*30)*Dn;
    const float* W; const float* bias; float* out;
    if (!isK) {
        if (l < Ln) { W = Wq + (size_t)l*Dn*Dn; bias = bq + l*Dn; }
        else        { W = Wsub;                 bias = bsub; }
        out = g_Qall;
    } else {
        if (l < Ln) { W = Wk + (size_t)l*Dn*Dn; bias = bk + l*Dn; }
        else        { W = Wobj;                 bias = bobj; }
        out = g_Kall;
    }
    out += ((size_t)(l*Bt + b)*Qn + tile*30)*Dn;
    gemm_tile<30>(src, W, bias, out);
}

__global__ void __launch_bounds__(256)
kernel_ab(const float* __restrict__ W1)
{
    int tile = blockIdx.x;
    int isB  = blockIdx.y;
    const float* src = (isB ? g_Kall : g_Qall) + (size_t)tile*30*Dn;
    const float* W   = W1 + (isB ? Dn*Dn : 0);
    float* out = (isB ? g_Bproj : g_Aproj) + (size_t)tile*30*Dn;
    gemm_tile<30>(src, W, nullptr, out);
}

__global__ void kernel_g(const float* __restrict__ Wg, const float* __restrict__ bg)
{
    int warp = threadIdx.x >> 5, lane = threadIdx.x & 31;
    int row = blockIdx.x*8 + warp;
    if (row >= LP1*Bt*Qn) return;
    int isK = blockIdx.y;
    const float* src = (isK ? g_Kall : g_Qall) + (size_t)row*Dn;
    const float* w   = Wg + (isK ? Dn : 0);
    float s = 0.f;
    #pragma unroll
    for (int u = 0; u < 8; u++) s = fmaf(src[lane + 32*u], w[lane + 32*u], s);
    #pragma unroll
    for (int off = 16; off > 0; off >>= 1) s += __shfl_xor_sync(0xffffffffu, s, off);
    if (lane == 0) {
        if (isK) g_gk[row] = s;
        else     g_gq[row] = s + bg[0];
    }
}

// Build W2 bf16 hi/lo B-fragments.
// mma m16n8k16 B(col) frag: lane -> g=lane>>2, tg=lane&3; reg r holds
// {B[k0+8r][n], B[k0+8r+1][n]} with k0 = kt*16 + tg*2, n = gnt*8 + g.
__global__ void kernel_prepw2(const float* __restrict__ W2)
{
    int idx = blockIdx.x*256 + threadIdx.x;   // 0..16383
    int lane = idx & 31;
    int gnt  = (idx >> 5) & 31;
    int kt   = idx >> 10;
    int g = lane >> 2, tg = lane & 3;
    int n  = gnt*8 + g;
    int k0 = kt*16 + tg*2;

    unsigned hr[2], lr[2];
    #pragma unroll
    for (int r = 0; r < 2; r++) {
        int ka = k0 + 8*r;
        float v0 = W2[(size_t)ka*Dn + n];
        float v1 = W2[(size_t)(ka+1)*Dn + n];
        __nv_bfloat16 h0 = __float2bfloat16(v0);
        __nv_bfloat16 h1 = __float2bfloat16(v1);
        __nv_bfloat16 l0 = __float2bfloat16(v0 - __bfloat162float(h0));
        __nv_bfloat16 l1 = __float2bfloat16(v1 - __bfloat162float(h1));
        __nv_bfloat162 hp; hp.x = h0; hp.y = h1;
        __nv_bfloat162 lp; lp.x = l0; lp.y = l1;
        hr[r] = *(unsigned*)&hp;
        lr[r] = *(unsigned*)&lp;
    }
    uint4 v; v.x = hr[0]; v.y = hr[1]; v.z = lr[0]; v.w = lr[1];
    g_W2frag[idx] = v;
}

// ---------------- main fused kernel ----------------
// 32i x 4j = 128 pairs per block, 256 threads (8 warps x 16 rows).
// Phase 1: exact fp32 gated combine -> h1 split bf16 hi/lo in smem.
// Phase 2: compensated bf16 HMMA GEMM vs W2 (hi*Whi + lo*Whi + hi*Wlo),
//          relu + b2, dot w3, quad-reduce, store 6 layer copies.
#define HS 264                      // h1 smem stride (bf16 elems): conflict-free a-frags
#define SM_GATES 0                  // 7*128*4   = 3584
#define SM_B2    3584               // 1024
#define SM_W3    4608               // 1024
#define SM_HHI   5632               // 128*264*2 = 67584
#define SM_HLO   (5632+67584)       // 67584
#define SMEM_TOTAL (5632 + 2*67584) // 140800

__device__ __forceinline__ void mma16816(float* c, const unsigned* a,
                                         unsigned b0, unsigned b1)
{
    asm volatile(
        "mma.sync.aligned.m16n8k16.row.col.f32.bf16.bf16.f32 "
        "{%0,%1,%2,%3}, {%4,%5,%6,%7}, {%8,%9}, {%0,%1,%2,%3};"
        : "+f"(c[0]), "+f"(c[1]), "+f"(c[2]), "+f"(c[3])
        : "r"(a[0]), "r"(a[1]), "r"(a[2]), "r"(a[3]), "r"(b0), "r"(b1));
}

__global__ void __launch_bounds__(256)
kernel_main(const float* __restrict__ b1, const float* __restrict__ b2g,
            const float* __restrict__ W3, const float* __restrict__ b3,
            float* __restrict__ out)
{
    extern __shared__ char smem[];
    float* gates = (float*)(smem + SM_GATES);
    float* b2s   = (float*)(smem + SM_B2);
    float* w3s   = (float*)(smem + SM_W3);
    __nv_bfloat16* hhi = (__nv_bfloat16*)(smem + SM_HHI);
    __nv_bfloat16* hlo = (__nv_bfloat16*)(smem + SM_HLO);

    int tid = threadIdx.x;
    int wid = tid >> 5, lane = tid & 31;
    int j0 = blockIdx.x*4;
    int i0 = blockIdx.y*32;
    int b  = blockIdx.z;

    b2s[tid] = b2g[tid];
    w3s[tid] = W3[tid];
    for (int t = tid; t < LP1*128; t += 256) {
        int l = t >> 7, p = t & 127;
        int i = min(i0 + (p >> 2), Qn - 1);
        int j = min(j0 + (p & 3),  Qn - 1);
        float z = g_gq[(l*Bt + b)*Qn + i] + g_gk[(l*Bt + b)*Qn + j];
        gates[t] = 1.f / (1.f + expf(-z));
    }
    __syncthreads();

    // ---- phase 1: h1 = relu(sum_l gate*(A_i + B_j) + b1), split bf16 hi/lo ----
    {
        int e = tid;
        float bvals[LP1][4];
        #pragma unroll
        for (int l = 0; l < LP1; l++) {
            const float* Bb = g_Bproj + (size_t)(l*Bt + b)*Qn*Dn;
            #pragma unroll
            for (int jj = 0; jj < 4; jj++)
                bvals[l][jj] = Bb[(size_t)min(j0 + jj, Qn - 1)*Dn + e];
        }
        float b1e = b1[e];
        for (int g4 = 0; g4 < 4; g4++) {
            float acc[32];
            #pragma unroll
            for (int p = 0; p < 32; p++) acc[p] = 0.f;
            #pragma unroll
            for (int l = 0; l < LP1; l++) {
                const float* Ab = g_Aproj + (size_t)(l*Bt + b)*Qn*Dn;
                float av[8];
                #pragma unroll
                for (int ii = 0; ii < 8; ii++)
                    av[ii] = Ab[(size_t)min(i0 + g4*8 + ii, Qn - 1)*Dn + e];
                const float* gl = &gates[l*128 + g4*32];
                #pragma unroll
                for (int ii = 0; ii < 8; ii++)
                    #pragma unroll
                    for (int jj = 0; jj < 4; jj++) {
                        int p = ii*4 + jj;
                        acc[p] = fmaf(gl[p], av[ii] + bvals[l][jj], acc[p]);
                    }
            }
            #pragma unroll
            for (int p = 0; p < 32; p++) {
                int row = g4*32 + p;
                float x = fmaxf(acc[p] + b1e, 0.f);
                __nv_bfloat16 hi = __float2bfloat16(x);
                __nv_bfloat16 lo = __float2bfloat16(x - __bfloat162float(hi));
                hhi[row*HS + e] = hi;
                hlo[row*HS + e] = lo;
            }
        }
    }
    __syncthreads();

    // ---- phase 2: compensated bf16 HMMA GEMM ----
    int g  = lane >> 2;
    int tg = lane & 3;
    int rb = wid * 16;               // warp's 16 rows
    float s_g = 0.f, s_g8 = 0.f;     // per-thread partial (rows rb+g, rb+8+g)

    #pragma unroll
    for (int nh = 0; nh < 2; nh++) {
        float acc[16][4];
        #pragma unroll
        for (int nt = 0; nt < 16; nt++)
            #pragma unroll
            for (int c = 0; c < 4; c++) acc[nt][c] = 0.f;

        #pragma unroll
        for (int kt = 0; kt < 16; kt++) {
            int k0 = kt*16 + tg*2;
            unsigned ahi[4], alo[4];
            ahi[0] = *(const unsigned*)&hhi[(rb + g    )*HS + k0];
            ahi[1] = *(const unsigned*)&hhi[(rb + g + 8)*HS + k0];
            ahi[2] = *(const unsigned*)&hhi[(rb + g    )*HS + k0 + 8];
            ahi[3] = *(const unsigned*)&hhi[(rb + g + 8)*HS + k0 + 8];
            alo[0] = *(const unsigned*)&hlo[(rb + g    )*HS + k0];
            alo[1] = *(const unsigned*)&hlo[(rb + g + 8)*HS + k0];
            alo[2] = *(const unsigned*)&hlo[(rb + g    )*HS + k0 + 8];
            alo[3] = *(const unsigned*)&hlo[(rb + g + 8)*HS + k0 + 8];

            const uint4* fr = &g_W2frag[((size_t)kt*32 + nh*16)*32 + lane];
            #pragma unroll
            for (int nt = 0; nt < 16; nt++) {
                uint4 bf = fr[nt*32];
                mma16816(acc[nt], ahi, bf.x, bf.y);   // hi * Whi
                mma16816(acc[nt], alo, bf.x, bf.y);   // lo * Whi
                mma16816(acc[nt], ahi, bf.z, bf.w);   // hi * Wlo
            }
        }

        // epilogue for this N-half
        #pragma unroll
        for (int nt = 0; nt < 16; nt++) {
            int n0 = (nh*16 + nt)*8 + tg*2;
            float w0 = w3s[n0], w1 = w3s[n0+1];
            float c0 = b2s[n0], c1 = b2s[n0+1];
            s_g  = fmaf(fmaxf(acc[nt][0] + c0, 0.f), w0, s_g);
            s_g  = fmaf(fmaxf(acc[nt][1] + c1, 0.f), w1, s_g);
            s_g8 = fmaf(fmaxf(acc[nt][2] + c0, 0.f), w0, s_g8);
            s_g8 = fmaf(fmaxf(acc[nt][3] + c1, 0.f), w1, s_g8);
        }
    }

    // reduce over the 4 threads of each row group
    #pragma unroll
    for (int off = 1; off <= 2; off <<= 1) {
        s_g  += __shfl_xor_sync(0xffffffffu, s_g,  off);
        s_g8 += __shfl_xor_sync(0xffffffffu, s_g8, off);
    }
    if (tg == 0) {
        float b3v = b3[0];
        int rows[2] = { rb + g, rb + 8 + g };
        float vals[2] = { s_g + b3v, s_g8 + b3v };
        #pragma unroll
        for (int u = 0; u < 2; u++) {
            int p = rows[u];
            int i = i0 + (p >> 2), j = j0 + (p & 3);
            if (i < Qn && j < Qn) {
                #pragma unroll
                for (int lay = 0; lay < Ln; lay++)
                    out[((size_t)(lay*Bt + b)*Qn + i)*Qn + j] = vals[u];
            }
        }
    }
}

extern "C" void kernel_launch(void* const* d_in, const int* in_sizes, int n_in,
                              void* d_out, int out_size)
{
    const float* hs   = (const float*)d_in[0];
    const float* Wq   = (const float*)d_in[1];
    const float* bq   = (const float*)d_in[2];
    const float* Wk   = (const float*)d_in[3];
    const float* bk   = (const float*)d_in[4];
    const float* Wsub = (const float*)d_in[5];
    const float* bsub = (const float*)d_in[6];
    const float* Wobj = (const float*)d_in[7];
    const float* bobj = (const float*)d_in[8];
    const float* Wg   = (const float*)d_in[9];
    const float* bg   = (const float*)d_in[10];
    const float* W1   = (const float*)d_in[11];
    const float* b1   = (const float*)d_in[12];
    const float* W2   = (const float*)d_in[13];
    const float* b2   = (const float*)d_in[14];
    const float* W3   = (const float*)d_in[15];
    const float* b3   = (const float*)d_in[16];
    float* out = (float*)d_out;

    cudaFuncSetAttribute(kernel_main, cudaFuncAttributeMaxDynamicSharedMemorySize, SMEM_TOTAL);

    kernel_qk    <<<dim3(10, 14, 2), 256>>>(hs, Wq, bq, Wk, bk, Wsub, bsub, Wobj, bobj);
    kernel_ab    <<<dim3(140, 2),    256>>>(W1);
    kernel_g     <<<dim3(525, 2),    256>>>(Wg, bg);
    kernel_prepw2<<<64,              256>>>(W2);
    kernel_main  <<<dim3(75, 10, 2), 256, SMEM_TOTAL>>>(b1, b2, W3, b3, out);
}

// round 5
// speedup vs baseline: 3.1375x; 1.2705x over previous
#include <cuda_runtime.h>
#include <cuda_fp16.h>
#include <math.h>

#define Ln 6
#define Bt 2
#define Qn 300
#define Dn 256
#define LP1 7

// ---------------- device scratch (no allocs allowed) ----------------
__device__ float g_Qall[LP1*Bt*Qn*Dn];
__device__ float g_Kall[LP1*Bt*Qn*Dn];
__device__ float g_Aproj[LP1*Bt*Qn*Dn];
__device__ float g_Bproj[LP1*Bt*Qn*Dn];
__device__ float g_gq[LP1*Bt*Qn];
__device__ float g_gk[LP1*Bt*Qn];
// W2 (256x256) as fp16 in mma.m16n8k16 B-fragment order:
// idx = ((kt*32 + gnt)*32 + lane), entry = uint2 {b_r0, b_r1}
__device__ uint2 g_W2frag[16*32*32];   // 128 KB

// ---------------- small GEMM helper ----------------
template<int ROWS>
__device__ __forceinline__ void gemm_tile(const float* __restrict__ src,
                                          const float* __restrict__ W,
                                          const float* __restrict__ bias,
                                          float* __restrict__ out)
{
    __shared__ float ssrc[ROWS*Dn];
    int tid = threadIdx.x;
    for (int idx = tid; idx < ROWS*Dn/4; idx += 256)
        ((float4*)ssrc)[idx] = ((const float4*)src)[idx];
    __syncthreads();

    int e = tid;
    float acc[ROWS];
    #pragma unroll
    for (int r = 0; r < ROWS; r++) acc[r] = 0.f;

    for (int d = 0; d < Dn; d += 4) {
        float w0 = W[(d+0)*Dn + e];
        float w1 = W[(d+1)*Dn + e];
        float w2 = W[(d+2)*Dn + e];
        float w3 = W[(d+3)*Dn + e];
        #pragma unroll
        for (int r = 0; r < ROWS; r++) {
            float4 s4 = *(const float4*)&ssrc[r*Dn + d];
            acc[r] = fmaf(s4.x, w0, acc[r]);
            acc[r] = fmaf(s4.y, w1, acc[r]);
            acc[r] = fmaf(s4.z, w2, acc[r]);
            acc[r] = fmaf(s4.w, w3, acc[r]);
        }
    }
    float bv = bias ? bias[e] : 0.f;
    #pragma unroll
    for (int r = 0; r < ROWS; r++) out[r*Dn + e] = acc[r] + bv;
}

__global__ void __launch_bounds__(256)
kernel_qk(const float* __restrict__ hs,
          const float* __restrict__ Wq,  const float* __restrict__ bq,
          const float* __restrict__ Wk,  const float* __restrict__ bk,
          const float* __restrict__ Wsub,const float* __restrict__ bsub,
          const float* __restrict__ Wobj,const float* __restrict__ bobj)
{
    int tile = blockIdx.x;
    int lb   = blockIdx.y;
    int isK  = blockIdx.z;
    int l = lb >> 1, b = lb & 1;
    int srcl = (l < Ln) ? l : (Ln - 1);
    const float* src = hs + ((size_t)(srcl*Bt + b)*Qn + tile*30)*Dn;
    const float* W; const float* bias; float* out;
    if (!isK) {
        if (l < Ln) { W = Wq + (size_t)l*Dn*Dn; bias = bq + l*Dn; }
        else        { W = Wsub;                 bias = bsub; }
        out = g_Qall;
    } else {
        if (l < Ln) { W = Wk + (size_t)l*Dn*Dn; bias = bk + l*Dn; }
        else        { W = Wobj;                 bias = bobj; }
        out = g_Kall;
    }
    out += ((size_t)(l*Bt + b)*Qn + tile*30)*Dn;
    gemm_tile<30>(src, W, bias, out);
}

__global__ void __launch_bounds__(256)
kernel_ab(const float* __restrict__ W1)
{
    int tile = blockIdx.x;
    int isB  = blockIdx.y;
    const float* src = (isB ? g_Kall : g_Qall) + (size_t)tile*30*Dn;
    const float* W   = W1 + (isB ? Dn*Dn : 0);
    float* out = (isB ? g_Bproj : g_Aproj) + (size_t)tile*30*Dn;
    gemm_tile<30>(src, W, nullptr, out);
}

__global__ void kernel_g(const float* __restrict__ Wg, const float* __restrict__ bg)
{
    int warp = threadIdx.x >> 5, lane = threadIdx.x & 31;
    int row = blockIdx.x*8 + warp;
    if (row >= LP1*Bt*Qn) return;
    int isK = blockIdx.y;
    const float* src = (isK ? g_Kall : g_Qall) + (size_t)row*Dn;
    const float* w   = Wg + (isK ? Dn : 0);
    float s = 0.f;
    #pragma unroll
    for (int u = 0; u < 8; u++) s = fmaf(src[lane + 32*u], w[lane + 32*u], s);
    #pragma unroll
    for (int off = 16; off > 0; off >>= 1) s += __shfl_xor_sync(0xffffffffu, s, off);
    if (lane == 0) {
        if (isK) g_gk[row] = s;
        else     g_gq[row] = s + bg[0];
    }
}

// Build W2 fp16 B-fragments (m16n8k16 col-major B frag layout).
__global__ void kernel_prepw2(const float* __restrict__ W2)
{
    int idx = blockIdx.x*256 + threadIdx.x;   // 0..16383
    int lane = idx & 31;
    int gnt  = (idx >> 5) & 31;
    int kt   = idx >> 10;
    int g = lane >> 2, tg = lane & 3;
    int n  = gnt*8 + g;
    int k0 = kt*16 + tg*2;

    unsigned hr[2];
    #pragma unroll
    for (int r = 0; r < 2; r++) {
        int ka = k0 + 8*r;
        __half2 hp;
        hp.x = __float2half(W2[(size_t)ka*Dn + n]);
        hp.y = __float2half(W2[(size_t)(ka+1)*Dn + n]);
        hr[r] = *(unsigned*)&hp;
    }
    uint2 v; v.x = hr[0]; v.y = hr[1];
    g_W2frag[idx] = v;
}

// ---------------- main fused kernel ----------------
// 32i x 4j = 128 pairs per block, 256 threads (8 warps x 16 rows).
// Phase 1: exact fp32 gated combine -> h1 split fp16 hi/lo in smem.
// Phase 2: 2-term fp16 HMMA GEMM vs W2h (xh*Wh + xl*Wh = x*Wh + O(2^-24)),
//          relu + b2, dot w3, quad-reduce, store 6 layer copies.
#define HS 264
#define SM_GATES 0                  // 7*128*4   = 3584
#define SM_B2    3584               // 1024
#define SM_W3    4608               // 1024
#define SM_HHI   5632               // 128*264*2 = 67584
#define SM_HLO   (5632+67584)
#define SMEM_TOTAL (5632 + 2*67584) // 140800

__device__ __forceinline__ void mma16816(float* c, const unsigned* a,
                                         unsigned b0, unsigned b1)
{
    asm volatile(
        "mma.sync.aligned.m16n8k16.row.col.f32.f16.f16.f32 "
        "{%0,%1,%2,%3}, {%4,%5,%6,%7}, {%8,%9}, {%0,%1,%2,%3};"
        : "+f"(c[0]), "+f"(c[1]), "+f"(c[2]), "+f"(c[3])
        : "r"(a[0]), "r"(a[1]), "r"(a[2]), "r"(a[3]), "r"(b0), "r"(b1));
}

__global__ void __launch_bounds__(256)
kernel_main(const float* __restrict__ b1, const float* __restrict__ b2g,
            const float* __restrict__ W3, const float* __restrict__ b3,
            float* __restrict__ out)
{
    extern __shared__ char smem[];
    float* gates = (float*)(smem + SM_GATES);
    float* b2s   = (float*)(smem + SM_B2);
    float* w3s   = (float*)(smem + SM_W3);
    __half* hhi = (__half*)(smem + SM_HHI);
    __half* hlo = (__half*)(smem + SM_HLO);

    int tid = threadIdx.x;
    int wid = tid >> 5, lane = tid & 31;
    int j0 = blockIdx.x*4;
    int i0 = blockIdx.y*32;
    int b  = blockIdx.z;

    b2s[tid] = b2g[tid];
    w3s[tid] = W3[tid];
    for (int t = tid; t < LP1*128; t += 256) {
        int l = t >> 7, p = t & 127;
        int i = min(i0 + (p >> 2), Qn - 1);
        int j = min(j0 + (p & 3),  Qn - 1);
        float z = g_gq[(l*Bt + b)*Qn + i] + g_gk[(l*Bt + b)*Qn + j];
        gates[t] = 1.f / (1.f + expf(-z));
    }
    __syncthreads();

    // ---- phase 1: h1 = relu(sum_l gate*(A_i + B_j) + b1), split fp16 hi/lo ----
    {
        int e = tid;
        float bvals[LP1][4];
        #pragma unroll
        for (int l = 0; l < LP1; l++) {
            const float* Bb = g_Bproj + (size_t)(l*Bt + b)*Qn*Dn;
            #pragma unroll
            for (int jj = 0; jj < 4; jj++)
                bvals[l][jj] = Bb[(size_t)min(j0 + jj, Qn - 1)*Dn + e];
        }
        float b1e = b1[e];
        for (int g4 = 0; g4 < 4; g4++) {
            float acc[32];
            #pragma unroll
            for (int p = 0; p < 32; p++) acc[p] = 0.f;
            #pragma unroll
            for (int l = 0; l < LP1; l++) {
                const float* Ab = g_Aproj + (size_t)(l*Bt + b)*Qn*Dn;
                float av[8];
                #pragma unroll
                for (int ii = 0; ii < 8; ii++)
                    av[ii] = Ab[(size_t)min(i0 + g4*8 + ii, Qn - 1)*Dn + e];
                const float* gl = &gates[l*128 + g4*32];
                #pragma unroll
                for (int ii = 0; ii < 8; ii++)
                    #pragma unroll
                    for (int jj = 0; jj < 4; jj++) {
                        int p = ii*4 + jj;
                        acc[p] = fmaf(gl[p], av[ii] + bvals[l][jj], acc[p]);
                    }
            }
            #pragma unroll
            for (int p = 0; p < 32; p++) {
                int row = g4*32 + p;
                float x = fmaxf(acc[p] + b1e, 0.f);
                __half hi = __float2half(x);
                __half lo = __float2half(x - __half2float(hi));
                hhi[row*HS + e] = hi;
                hlo[row*HS + e] = lo;
            }
        }
    }
    __syncthreads();

    // ---- phase 2: 2-term fp16 HMMA GEMM ----
    int g  = lane >> 2;
    int tg = lane & 3;
    int rb = wid * 16;
    float s_g = 0.f, s_g8 = 0.f;

    #pragma unroll
    for (int nh = 0; nh < 2; nh++) {
        float acc[16][4];
        #pragma unroll
        for (int nt = 0; nt < 16; nt++)
            #pragma unroll
            for (int c = 0; c < 4; c++) acc[nt][c] = 0.f;

        #pragma unroll
        for (int kt = 0; kt < 16; kt++) {
            int k0 = kt*16 + tg*2;
            unsigned ahi[4], alo[4];
            ahi[0] = *(const unsigned*)&hhi[(rb + g    )*HS + k0];
            ahi[1] = *(const unsigned*)&hhi[(rb + g + 8)*HS + k0];
            ahi[2] = *(const unsigned*)&hhi[(rb + g    )*HS + k0 + 8];
            ahi[3] = *(const unsigned*)&hhi[(rb + g + 8)*HS + k0 + 8];
            alo[0] = *(const unsigned*)&hlo[(rb + g    )*HS + k0];
            alo[1] = *(const unsigned*)&hlo[(rb + g + 8)*HS + k0];
            alo[2] = *(const unsigned*)&hlo[(rb + g    )*HS + k0 + 8];
            alo[3] = *(const unsigned*)&hlo[(rb + g + 8)*HS + k0 + 8];

            const uint2* fr = &g_W2frag[((size_t)kt*32 + nh*16)*32 + lane];
            #pragma unroll
            for (int nt = 0; nt < 16; nt++) {
                uint2 bf = fr[nt*32];
                mma16816(acc[nt], ahi, bf.x, bf.y);   // xh * Wh
                mma16816(acc[nt], alo, bf.x, bf.y);   // xl * Wh
            }
        }

        #pragma unroll
        for (int nt = 0; nt < 16; nt++) {
            int n0 = (nh*16 + nt)*8 + tg*2;
            float w0 = w3s[n0], w1 = w3s[n0+1];
            float c0 = b2s[n0], c1 = b2s[n0+1];
            s_g  = fmaf(fmaxf(acc[nt][0] + c0, 0.f), w0, s_g);
            s_g  = fmaf(fmaxf(acc[nt][1] + c1, 0.f), w1, s_g);
            s_g8 = fmaf(fmaxf(acc[nt][2] + c0, 0.f), w0, s_g8);
            s_g8 = fmaf(fmaxf(acc[nt][3] + c1, 0.f), w1, s_g8);
        }
    }

    #pragma unroll
    for (int off = 1; off <= 2; off <<= 1) {
        s_g  += __shfl_xor_sync(0xffffffffu, s_g,  off);
        s_g8 += __shfl_xor_sync(0xffffffffu, s_g8, off);
    }
    if (tg == 0) {
        float b3v = b3[0];
        int rows[2] = { rb + g, rb + 8 + g };
        float vals[2] = { s_g + b3v, s_g8 + b3v };
        #pragma unroll
        for (int u = 0; u < 2; u++) {
            int p = rows[u];
            int i = i0 + (p >> 2), j = j0 + (p & 3);
            if (i < Qn && j < Qn) {
                #pragma unroll
                for (int lay = 0; lay < Ln; lay++)
                    out[((size_t)(lay*Bt + b)*Qn + i)*Qn + j] = vals[u];
            }
        }
    }
}

extern "C" void kernel_launch(void* const* d_in, const int* in_sizes, int n_in,
                              void* d_out, int out_size)
{
    const float* hs   = (const float*)d_in[0];
    const float* Wq   = (const float*)d_in[1];
    const float* bq   = (const float*)d_in[2];
    const float* Wk   = (const float*)d_in[3];
    const float* bk   = (const float*)d_in[4];
    const float* Wsub = (const float*)d_in[5];
    const float* bsub = (const float*)d_in[6];
    const float* Wobj = (const float*)d_in[7];
    const float* bobj = (const float*)d_in[8];
    const float* Wg   = (const float*)d_in[9];
    const float* bg   = (const float*)d_in[10];
    const float* W1   = (const float*)d_in[11];
    const float* b1   = (const float*)d_in[12];
    const float* W2   = (const float*)d_in[13];
    const float* b2   = (const float*)d_in[14];
    const float* W3   = (const float*)d_in[15];
    const float* b3   = (const float*)d_in[16];
    float* out = (float*)d_out;

    cudaFuncSetAttribute(kernel_main, cudaFuncAttributeMaxDynamicSharedMemorySize, SMEM_TOTAL);

    kernel_qk    <<<dim3(10, 14, 2), 256>>>(hs, Wq, bq, Wk, bk, Wsub, bsub, Wobj, bobj);
    kernel_ab    <<<dim3(140, 2),    256>>>(W1);
    kernel_g     <<<dim3(525, 2),    256>>>(Wg, bg);
    kernel_prepw2<<<64,              256>>>(W2);
    kernel_main  <<<dim3(75, 10, 2), 256, SMEM_TOTAL>>>(b1, b2, W3, b3, out);
}

// round 6
// speedup vs baseline: 3.4959x; 1.1142x over previous
#include <cuda_runtime.h>
#include <cuda_fp16.h>
#include <math.h>

#define Ln 6
#define Bt 2
#define Qn 300
#define Dn 256
#define LP1 7

// ---------------- device scratch (no allocs allowed) ----------------
__device__ float g_Qall[LP1*Bt*Qn*Dn];
__device__ float g_Kall[LP1*Bt*Qn*Dn];
__device__ float g_Aproj[LP1*Bt*Qn*Dn];
__device__ float g_Bproj[LP1*Bt*Qn*Dn];
__device__ float g_gq[LP1*Bt*Qn];
__device__ float g_gk[LP1*Bt*Qn];
// W2 (256x256) as fp16 in mma.m16n8k16 B-fragment order:
// idx = ((kt*32 + gnt)*32 + lane), entry = uint2 {b_r0, b_r1}
__device__ uint2 g_W2frag[16*32*32];   // 128 KB

// ---------------- small GEMM helper ----------------
template<int ROWS>
__device__ __forceinline__ void gemm_tile(const float* __restrict__ src,
                                          const float* __restrict__ W,
                                          const float* __restrict__ bias,
                                          float* __restrict__ out)
{
    __shared__ float ssrc[ROWS*Dn];
    int tid = threadIdx.x;
    for (int idx = tid; idx < ROWS*Dn/4; idx += 256)
        ((float4*)ssrc)[idx] = ((const float4*)src)[idx];
    __syncthreads();

    int e = tid;
    float acc[ROWS];
    #pragma unroll
    for (int r = 0; r < ROWS; r++) acc[r] = 0.f;

    for (int d = 0; d < Dn; d += 4) {
        float w0 = W[(d+0)*Dn + e];
        float w1 = W[(d+1)*Dn + e];
        float w2 = W[(d+2)*Dn + e];
        float w3 = W[(d+3)*Dn + e];
        #pragma unroll
        for (int r = 0; r < ROWS; r++) {
            float4 s4 = *(const float4*)&ssrc[r*Dn + d];
            acc[r] = fmaf(s4.x, w0, acc[r]);
            acc[r] = fmaf(s4.y, w1, acc[r]);
            acc[r] = fmaf(s4.z, w2, acc[r]);
            acc[r] = fmaf(s4.w, w3, acc[r]);
        }
    }
    float bv = bias ? bias[e] : 0.f;
    #pragma unroll
    for (int r = 0; r < ROWS; r++) out[r*Dn + e] = acc[r] + bv;
}

__global__ void __launch_bounds__(256)
kernel_qk(const float* __restrict__ hs,
          const float* __restrict__ Wq,  const float* __restrict__ bq,
          const float* __restrict__ Wk,  const float* __restrict__ bk,
          const float* __restrict__ Wsub,const float* __restrict__ bsub,
          const float* __restrict__ Wobj,const float* __restrict__ bobj)
{
    int tile = blockIdx.x;
    int lb   = blockIdx.y;
    int isK  = blockIdx.z;
    int l = lb >> 1, b = lb & 1;
    int srcl = (l < Ln) ? l : (Ln - 1);
    const float* src = hs + ((size_t)(srcl*Bt + b)*Qn + tile*30)*Dn;
    const float* W; const float* bias; float* out;
    if (!isK) {
        if (l < Ln) { W = Wq + (size_t)l*Dn*Dn; bias = bq + l*Dn; }
        else        { W = Wsub;                 bias = bsub; }
        out = g_Qall;
    } else {
        if (l < Ln) { W = Wk + (size_t)l*Dn*Dn; bias = bk + l*Dn; }
        else        { W = Wobj;                 bias = bobj; }
        out = g_Kall;
    }
    out += ((size_t)(l*Bt + b)*Qn + tile*30)*Dn;
    gemm_tile<30>(src, W, bias, out);
}

__global__ void __launch_bounds__(256)
kernel_ab(const float* __restrict__ W1)
{
    int tile = blockIdx.x;
    int isB  = blockIdx.y;
    const float* src = (isB ? g_Kall : g_Qall) + (size_t)tile*30*Dn;
    const float* W   = W1 + (isB ? Dn*Dn : 0);
    float* out = (isB ? g_Bproj : g_Aproj) + (size_t)tile*30*Dn;
    gemm_tile<30>(src, W, nullptr, out);
}

__global__ void kernel_g(const float* __restrict__ Wg, const float* __restrict__ bg)
{
    int warp = threadIdx.x >> 5, lane = threadIdx.x & 31;
    int row = blockIdx.x*8 + warp;
    if (row >= LP1*Bt*Qn) return;
    int isK = blockIdx.y;
    const float* src = (isK ? g_Kall : g_Qall) + (size_t)row*Dn;
    const float* w   = Wg + (isK ? Dn : 0);
    float s = 0.f;
    #pragma unroll
    for (int u = 0; u < 8; u++) s = fmaf(src[lane + 32*u], w[lane + 32*u], s);
    #pragma unroll
    for (int off = 16; off > 0; off >>= 1) s += __shfl_xor_sync(0xffffffffu, s, off);
    if (lane == 0) {
        if (isK) g_gk[row] = s;
        else     g_gq[row] = s + bg[0];
    }
}

// Build W2 fp16 B-fragments (m16n8k16 col-major B frag layout).
__global__ void kernel_prepw2(const float* __restrict__ W2)
{
    int idx = blockIdx.x*256 + threadIdx.x;   // 0..16383
    int lane = idx & 31;
    int gnt  = (idx >> 5) & 31;
    int kt   = idx >> 10;
    int g = lane >> 2, tg = lane & 3;
    int n  = gnt*8 + g;
    int k0 = kt*16 + tg*2;

    unsigned hr[2];
    #pragma unroll
    for (int r = 0; r < 2; r++) {
        int ka = k0 + 8*r;
        __half2 hp;
        hp.x = __float2half(W2[(size_t)ka*Dn + n]);
        hp.y = __float2half(W2[(size_t)(ka+1)*Dn + n]);
        hr[r] = *(unsigned*)&hp;
    }
    uint2 v; v.x = hr[0]; v.y = hr[1];
    g_W2frag[idx] = v;
}

// ---------------- main fused kernel ----------------
// 32i x 4j = 128 pairs per block, 256 threads (8 warps x 16 rows).
// Phase 1: exact fp32 gated combine -> h1 fp16 in smem.
// Phase 2: single-term fp16 HMMA GEMM vs W2h, relu + b2, dot w3,
//          quad-reduce, store 6 layer copies.
#define HS 264
#define SM_GATES 0                  // 7*128*4   = 3584
#define SM_B2    3584               // 1024
#define SM_W3    4608               // 1024
#define SM_HHI   5632               // 128*264*2 = 67584
#define SMEM_TOTAL (5632 + 67584)   // 73216

__device__ __forceinline__ void mma16816(float* c, const unsigned* a,
                                         unsigned b0, unsigned b1)
{
    asm volatile(
        "mma.sync.aligned.m16n8k16.row.col.f32.f16.f16.f32 "
        "{%0,%1,%2,%3}, {%4,%5,%6,%7}, {%8,%9}, {%0,%1,%2,%3};"
        : "+f"(c[0]), "+f"(c[1]), "+f"(c[2]), "+f"(c[3])
        : "r"(a[0]), "r"(a[1]), "r"(a[2]), "r"(a[3]), "r"(b0), "r"(b1));
}

__global__ void __launch_bounds__(256)
kernel_main(const float* __restrict__ b1, const float* __restrict__ b2g,
            const float* __restrict__ W3, const float* __restrict__ b3,
            float* __restrict__ out)
{
    extern __shared__ char smem[];
    float* gates = (float*)(smem + SM_GATES);
    float* b2s   = (float*)(smem + SM_B2);
    float* w3s   = (float*)(smem + SM_W3);
    __half* hhi = (__half*)(smem + SM_HHI);

    int tid = threadIdx.x;
    int wid = tid >> 5, lane = tid & 31;
    int j0 = blockIdx.x*4;
    int i0 = blockIdx.y*32;
    int b  = blockIdx.z;

    b2s[tid] = b2g[tid];
    w3s[tid] = W3[tid];
    for (int t = tid; t < LP1*128; t += 256) {
        int l = t >> 7, p = t & 127;
        int i = min(i0 + (p >> 2), Qn - 1);
        int j = min(j0 + (p & 3),  Qn - 1);
        float z = g_gq[(l*Bt + b)*Qn + i] + g_gk[(l*Bt + b)*Qn + j];
        gates[t] = 1.f / (1.f + expf(-z));
    }
    __syncthreads();

    // ---- phase 1: h1 = relu(sum_l gate*(A_i + B_j) + b1) -> fp16 smem ----
    {
        int e = tid;
        float bvals[LP1][4];
        #pragma unroll
        for (int l = 0; l < LP1; l++) {
            const float* Bb = g_Bproj + (size_t)(l*Bt + b)*Qn*Dn;
            #pragma unroll
            for (int jj = 0; jj < 4; jj++)
                bvals[l][jj] = Bb[(size_t)min(j0 + jj, Qn - 1)*Dn + e];
        }
        float b1e = b1[e];
        for (int g4 = 0; g4 < 4; g4++) {
            float acc[32];
            #pragma unroll
            for (int p = 0; p < 32; p++) acc[p] = 0.f;
            #pragma unroll
            for (int l = 0; l < LP1; l++) {
                const float* Ab = g_Aproj + (size_t)(l*Bt + b)*Qn*Dn;
                float av[8];
                #pragma unroll
                for (int ii = 0; ii < 8; ii++)
                    av[ii] = Ab[(size_t)min(i0 + g4*8 + ii, Qn - 1)*Dn + e];
                const float* gl = &gates[l*128 + g4*32];
                #pragma unroll
                for (int ii = 0; ii < 8; ii++)
                    #pragma unroll
                    for (int jj = 0; jj < 4; jj++) {
                        int p = ii*4 + jj;
                        acc[p] = fmaf(gl[p], av[ii] + bvals[l][jj], acc[p]);
                    }
            }
            #pragma unroll
            for (int p = 0; p < 32; p++) {
                int row = g4*32 + p;
                hhi[row*HS + e] = __float2half(fmaxf(acc[p] + b1e, 0.f));
            }
        }
    }
    __syncthreads();

    // ---- phase 2: single-term fp16 HMMA GEMM ----
    int g  = lane >> 2;
    int tg = lane & 3;
    int rb = wid * 16;
    float s_g = 0.f, s_g8 = 0.f;

    #pragma unroll
    for (int nh = 0; nh < 2; nh++) {
        float acc[16][4];
        #pragma unroll
        for (int nt = 0; nt < 16; nt++)
            #pragma unroll
            for (int c = 0; c < 4; c++) acc[nt][c] = 0.f;

        #pragma unroll
        for (int kt = 0; kt < 16; kt++) {
            int k0 = kt*16 + tg*2;
            unsigned ahi[4];
            ahi[0] = *(const unsigned*)&hhi[(rb + g    )*HS + k0];
            ahi[1] = *(const unsigned*)&hhi[(rb + g + 8)*HS + k0];
            ahi[2] = *(const unsigned*)&hhi[(rb + g    )*HS + k0 + 8];
            ahi[3] = *(const unsigned*)&hhi[(rb + g + 8)*HS + k0 + 8];

            const uint2* fr = &g_W2frag[((size_t)kt*32 + nh*16)*32 + lane];
            #pragma unroll
            for (int nt = 0; nt < 16; nt++) {
                uint2 bf = fr[nt*32];
                mma16816(acc[nt], ahi, bf.x, bf.y);
            }
        }

        #pragma unroll
        for (int nt = 0; nt < 16; nt++) {
            int n0 = (nh*16 + nt)*8 + tg*2;
            float w0 = w3s[n0], w1 = w3s[n0+1];
            float c0 = b2s[n0], c1 = b2s[n0+1];
            s_g  = fmaf(fmaxf(acc[nt][0] + c0, 0.f), w0, s_g);
            s_g  = fmaf(fmaxf(acc[nt][1] + c1, 0.f), w1, s_g);
            s_g8 = fmaf(fmaxf(acc[nt][2] + c0, 0.f), w0, s_g8);
            s_g8 = fmaf(fmaxf(acc[nt][3] + c1, 0.f), w1, s_g8);
        }
    }

    #pragma unroll
    for (int off = 1; off <= 2; off <<= 1) {
        s_g  += __shfl_xor_sync(0xffffffffu, s_g,  off);
        s_g8 += __shfl_xor_sync(0xffffffffu, s_g8, off);
    }
    if (tg == 0) {
        float b3v = b3[0];
        int rows[2] = { rb + g, rb + 8 + g };
        float vals[2] = { s_g + b3v, s_g8 + b3v };
        #pragma unroll
        for (int u = 0; u < 2; u++) {
            int p = rows[u];
            int i = i0 + (p >> 2), j = j0 + (p & 3);
            if (i < Qn && j < Qn) {
                #pragma unroll
                for (int lay = 0; lay < Ln; lay++)
                    out[((size_t)(lay*Bt + b)*Qn + i)*Qn + j] = vals[u];
            }
        }
    }
}

extern "C" void kernel_launch(void* const* d_in, const int* in_sizes, int n_in,
                              void* d_out, int out_size)
{
    const float* hs   = (const float*)d_in[0];
    const float* Wq   = (const float*)d_in[1];
    const float* bq   = (const float*)d_in[2];
    const float* Wk   = (const float*)d_in[3];
    const float* bk   = (const float*)d_in[4];
    const float* Wsub = (const float*)d_in[5];
    const float* bsub = (const float*)d_in[6];
    const float* Wobj = (const float*)d_in[7];
    const float* bobj = (const float*)d_in[8];
    const float* Wg   = (const float*)d_in[9];
    const float* bg   = (const float*)d_in[10];
    const float* W1   = (const float*)d_in[11];
    const float* b1   = (const float*)d_in[12];
    const float* W2   = (const float*)d_in[13];
    const float* b2   = (const float*)d_in[14];
    const float* W3   = (const float*)d_in[15];
    const float* b3   = (const float*)d_in[16];
    float* out = (float*)d_out;

    cudaFuncSetAttribute(kernel_main, cudaFuncAttributeMaxDynamicSharedMemorySize, SMEM_TOTAL);

    kernel_qk    <<<dim3(10, 14, 2), 256>>>(hs, Wq, bq, Wk, bk, Wsub, bsub, Wobj, bobj);
    kernel_ab    <<<dim3(140, 2),    256>>>(W1);
    kernel_g     <<<dim3(525, 2),    256>>>(Wg, bg);
    kernel_prepw2<<<64,              256>>>(W2);
    kernel_main  <<<dim3(75, 10, 2), 256, SMEM_TOTAL>>>(b1, b2, W3, b3, out);
}